// round 8
// baseline (speedup 1.0000x reference)
#include <cuda_runtime.h>
#include <cuda_bf16.h>
#include <cstdint>

typedef uint32_t u32;

// ---- bf16 helpers ----
__device__ __forceinline__ u32 bf2(float lo, float hi) {   // lo -> low 16 bits
    u32 r; asm("cvt.rn.bf16x2.f32 %0, %1, %2;" : "=r"(r) : "f"(hi), "f"(lo)); return r;
}
__device__ __forceinline__ float lo_f32(u32 p) { return __uint_as_float(p << 16); }
__device__ __forceinline__ float hi_f32(u32 p) { return __uint_as_float(p & 0xFFFF0000u); }
__device__ __forceinline__ float rbf(float v) {
    return __bfloat162float(__float2bfloat16(v));
}

// ---- f16x2 helpers (packed activations: 2 cells per op) ----
__device__ __forceinline__ u32 pk16(float lo, float hi) {  // lo -> low half
    u32 r; asm("cvt.rn.f16x2.f32 %0, %1, %2;" : "=r"(r) : "f"(hi), "f"(lo)); return r;
}
__device__ __forceinline__ u32 th2(u32 x) {                // 2x tanh in 1 MUFU
    u32 r; asm("tanh.approx.f16x2 %0, %1;" : "=r"(r) : "r"(x)); return r;
}
__device__ __forceinline__ u32 sg2(u32 t) {                // t*0.5 + 0.5 (packed)
    u32 r; asm("fma.rn.f16x2 %0, %1, %2, %2;" : "=r"(r) : "r"(t), "r"(0x38003800u)); return r;
}
__device__ __forceinline__ u32 hmul2(u32 a, u32 b) {
    u32 r; asm("mul.rn.f16x2 %0, %1, %2;" : "=r"(r) : "r"(a), "r"(b)); return r;
}
__device__ __forceinline__ void up16(u32 p, float& lo, float& hi) {
    asm("{ .reg .b16 l, h; mov.b32 {l, h}, %2; cvt.f32.f16 %0, l; cvt.f32.f16 %1, h; }"
        : "=f"(lo), "=f"(hi) : "r"(p));
}

// D += A * B  (m16n8k16, bf16 in, f32 accum), accumulate in place
__device__ __forceinline__ void mma16816(float* d, u32 a0, u32 a1, u32 a2, u32 a3,
                                         u32 b0, u32 b1) {
    asm("mma.sync.aligned.m16n8k16.row.col.f32.bf16.bf16.f32 "
        "{%0,%1,%2,%3}, {%4,%5,%6,%7}, {%8,%9}, {%0,%1,%2,%3};"
        : "+f"(d[0]), "+f"(d[1]), "+f"(d[2]), "+f"(d[3])
        : "r"(a0), "r"(a1), "r"(a2), "r"(a3), "r"(b0), "r"(b1));
}

// LSTM cell update for 4 cells (2 f16x2 pairs): gates i,f,o prescaled by 0.5
// (sigmoid = tanh2 + packed fma). c kept in f32; gate nonlinearity in f16x2.
__device__ __forceinline__ void cell4(const float* di, const float* df,
                                      const float* dg, const float* dq,
                                      float* c, float* h) {
#pragma unroll
    for (int p = 0; p < 2; p++) {
        int j = p * 2;
        u32 iv = sg2(th2(pk16(di[j], di[j+1])));
        u32 fv = sg2(th2(pk16(df[j], df[j+1])));
        u32 gv = th2(pk16(dg[j], dg[j+1]));
        u32 ov = sg2(th2(pk16(dq[j], dq[j+1])));
        u32 ig = hmul2(iv, gv);
        float ig0, ig1, f0, f1;
        up16(ig, ig0, ig1);
        up16(fv, f0, f1);
        c[j]   = fmaf(f0, c[j],   ig0);
        c[j+1] = fmaf(f1, c[j+1], ig1);
        u32 hv = hmul2(ov, th2(pk16(c[j], c[j+1])));
        up16(hv, h[j], h[j+1]);
    }
}

// One warp = 16 sequences. Per step, per gate:
//  L0: d0 = bias + Wih*x (exact f32 FFMA); MMA[h_hi|h_lo]x[Whi|Whi];
//      e0 = MMA[h_hi|0]x[Wlo|Wlo]  => full hi/lo product, all depth-1.
//  L1: d1 = bias + MMA[h0hi|h1hi]x[Bhi]; e1 = MMA[h0lo|h1lo]x[Bhi]
//      + MMA[h0hi|h1hi]x[Blo].
// Software pipeline: L0(t+1) issued before consuming L1(t).
// Activations in f16x2 (tanh.approx.f16x2): 20 MUFU/warp-step vs 40 for f32.
__global__ void __launch_bounds__(128) lstm_mma3(
    const float* __restrict__ input,
    const float* __restrict__ w_ih0, const float* __restrict__ w_hh0,
    const float* __restrict__ b_ih0, const float* __restrict__ b_hh0,
    const float* __restrict__ w_ih1, const float* __restrict__ w_hh1,
    const float* __restrict__ b_ih1, const float* __restrict__ b_hh1,
    const float* __restrict__ w_mlp, const float* __restrict__ b_mlp,
    float* __restrict__ out, int B)
{
    const int T = 256;
    int lane = threadIdx.x & 31;
    int gid  = lane >> 2;
    int tg   = lane & 3;
    int warp = (blockIdx.x * (blockDim.x >> 5)) + (threadIdx.x >> 5);
    int wbase = warp * 16;

    int rA = wbase + gid;
    int rB = wbase + gid + 8;
    int rAc = (rA < B) ? rA : (B - 1);
    int rBc = (rB < B) ? rB : (B - 1);

    // ---- weights: bf16 hi+lo B fragments, f32 x-weights, f32 biases ----
    u32 B0h[4], B0l[4], B1ah[4], B1bh[4], B1al[4], B1bl[4];
    float wi00[4], wi01[4], wi10[4], wi11[4];
    float be0[4], bo0[4], be1[4], bo1[4];
#pragma unroll
    for (int g = 0; g < 4; g++) {
        int wr = g * 8 + gid;
        float s = (g == 2) ? 1.0f : 0.5f;
        float a0 = s * w_hh0[wr * 8 + tg * 2], a1 = s * w_hh0[wr * 8 + tg * 2 + 1];
        float u0 = s * w_ih1[wr * 8 + tg * 2], u1 = s * w_ih1[wr * 8 + tg * 2 + 1];
        float v0 = s * w_hh1[wr * 8 + tg * 2], v1 = s * w_hh1[wr * 8 + tg * 2 + 1];
        B0h[g]  = bf2(rbf(a0), rbf(a1));  B0l[g]  = bf2(a0 - rbf(a0), a1 - rbf(a1));
        B1ah[g] = bf2(rbf(u0), rbf(u1));  B1al[g] = bf2(u0 - rbf(u0), u1 - rbf(u1));
        B1bh[g] = bf2(rbf(v0), rbf(v1));  B1bl[g] = bf2(v0 - rbf(v0), v1 - rbf(v1));
        int cE = g * 8 + tg * 2;
        wi00[g] = s * w_ih0[cE * 2];         wi01[g] = s * w_ih0[cE * 2 + 1];
        wi10[g] = s * w_ih0[(cE + 1) * 2];   wi11[g] = s * w_ih0[(cE + 1) * 2 + 1];
        be0[g] = s * (b_ih0[cE] + b_hh0[cE]);
        bo0[g] = s * (b_ih0[cE + 1] + b_hh0[cE + 1]);
        be1[g] = s * (b_ih1[cE] + b_hh1[cE]);
        bo1[g] = s * (b_ih1[cE + 1] + b_hh1[cE + 1]);
    }

    // ---- state ----
    float c0[4] = {0.f, 0.f, 0.f, 0.f};
    float c1[4] = {0.f, 0.f, 0.f, 0.f};
    float h1f[4] = {0.f, 0.f, 0.f, 0.f};
    u32 h0hL = 0, h0hH = 0, h0lL = 0, h0lH = 0;
    u32 h1hL = 0, h1hH = 0, h1lL = 0, h1lH = 0;

    const float2* xr = reinterpret_cast<const float2*>(input);

    // ---- prologue: L0(0) = bias + Wih*x(0); h0(-1)=0 so no MMA ----
    float d0[4][4], e0[4][4];
    {
        float2 xA = __ldg(&xr[(size_t)rAc * T]);
        float2 xB = __ldg(&xr[(size_t)rBc * T]);
#pragma unroll
        for (int g = 0; g < 4; g++) {
            d0[g][0] = fmaf(wi01[g], xA.y, fmaf(wi00[g], xA.x, be0[g]));
            d0[g][1] = fmaf(wi11[g], xA.y, fmaf(wi10[g], xA.x, bo0[g]));
            d0[g][2] = fmaf(wi01[g], xB.y, fmaf(wi00[g], xB.x, be0[g]));
            d0[g][3] = fmaf(wi11[g], xB.y, fmaf(wi10[g], xB.x, bo0[g]));
            e0[g][0] = 0.f; e0[g][1] = 0.f; e0[g][2] = 0.f; e0[g][3] = 0.f;
        }
    }

    for (int t = 0; t < T; t++) {
        // ---- consume L0(t) -> h0(t) ----
        float gi[4], gf[4], gg[4], gq[4];
#pragma unroll
        for (int j = 0; j < 4; j++) {
            gi[j] = d0[0][j] + e0[0][j];
            gf[j] = d0[1][j] + e0[1][j];
            gg[j] = d0[2][j] + e0[2][j];
            gq[j] = d0[3][j] + e0[3][j];
        }
        float h0f[4];
        cell4(gi, gf, gg, gq, c0, h0f);
        h0hL = bf2(h0f[0], h0f[1]);
        h0lL = bf2(h0f[0] - lo_f32(h0hL), h0f[1] - hi_f32(h0hL));
        h0hH = bf2(h0f[2], h0f[3]);
        h0lH = bf2(h0f[2] - lo_f32(h0hH), h0f[3] - hi_f32(h0hH));

        // ---- issue L1(t): main (d1) + corrections (e1) ----
        float d1[4][4], e1[4][4];
#pragma unroll
        for (int g = 0; g < 4; g++) {
            d1[g][0] = be1[g]; d1[g][1] = bo1[g];
            d1[g][2] = be1[g]; d1[g][3] = bo1[g];
            e1[g][0] = 0.f; e1[g][1] = 0.f; e1[g][2] = 0.f; e1[g][3] = 0.f;
            mma16816(d1[g], h0hL, h0hH, h1hL, h1hH, B1ah[g], B1bh[g]);
            mma16816(e1[g], h0lL, h0lH, h1lL, h1lH, B1ah[g], B1bh[g]);
            mma16816(e1[g], h0hL, h0hH, h1hL, h1hH, B1al[g], B1bl[g]);
        }

        // ---- issue L0(t+1): exact x/bias init + hi/lo MMAs ----
        {
            int tn = (t < T - 1) ? (t + 1) : t;
            float2 xA = __ldg(&xr[(size_t)rAc * T + tn]);
            float2 xB = __ldg(&xr[(size_t)rBc * T + tn]);
#pragma unroll
            for (int g = 0; g < 4; g++) {
                d0[g][0] = fmaf(wi01[g], xA.y, fmaf(wi00[g], xA.x, be0[g]));
                d0[g][1] = fmaf(wi11[g], xA.y, fmaf(wi10[g], xA.x, bo0[g]));
                d0[g][2] = fmaf(wi01[g], xB.y, fmaf(wi00[g], xB.x, be0[g]));
                d0[g][3] = fmaf(wi11[g], xB.y, fmaf(wi10[g], xB.x, bo0[g]));
                e0[g][0] = 0.f; e0[g][1] = 0.f; e0[g][2] = 0.f; e0[g][3] = 0.f;
                mma16816(d0[g], h0hL, h0hH, h0lL, h0lH, B0h[g], B0h[g]);
                mma16816(e0[g], h0hL, h0hH, 0u, 0u, B0l[g], B0l[g]);
            }
        }

        // ---- consume L1(t) -> h1(t) ----
#pragma unroll
        for (int j = 0; j < 4; j++) {
            gi[j] = d1[0][j] + e1[0][j];
            gf[j] = d1[1][j] + e1[1][j];
            gg[j] = d1[2][j] + e1[2][j];
            gq[j] = d1[3][j] + e1[3][j];
        }
        cell4(gi, gf, gg, gq, c1, h1f);
        h1hL = bf2(h1f[0], h1f[1]);
        h1lL = bf2(h1f[0] - lo_f32(h1hL), h1f[1] - hi_f32(h1hL));
        h1hH = bf2(h1f[2], h1f[3]);
        h1lH = bf2(h1f[2] - lo_f32(h1hH), h1f[3] - hi_f32(h1hH));
    }

    // ================= MLP head =================
    int hidE = tg * 2;
    float p0A = h1f[0] * w_mlp[hidE]     + h1f[1] * w_mlp[hidE + 1];
    float p1A = h1f[0] * w_mlp[8 + hidE] + h1f[1] * w_mlp[8 + hidE + 1];
    float p0B = h1f[2] * w_mlp[hidE]     + h1f[3] * w_mlp[hidE + 1];
    float p1B = h1f[2] * w_mlp[8 + hidE] + h1f[3] * w_mlp[8 + hidE + 1];
#pragma unroll
    for (int off = 1; off < 4; off <<= 1) {
        p0A += __shfl_xor_sync(0xffffffffu, p0A, off);
        p1A += __shfl_xor_sync(0xffffffffu, p1A, off);
        p0B += __shfl_xor_sync(0xffffffffu, p0B, off);
        p1B += __shfl_xor_sync(0xffffffffu, p1B, off);
    }
    if (tg == 0) {
        if (rA < B) {
            float2 o; o.x = p0A + b_mlp[0]; o.y = p1A + b_mlp[1];
            reinterpret_cast<float2*>(out)[rA] = o;
        }
        if (rB < B) {
            float2 o; o.x = p0B + b_mlp[0]; o.y = p1B + b_mlp[1];
            reinterpret_cast<float2*>(out)[rB] = o;
        }
    }
}

extern "C" void kernel_launch(void* const* d_in, const int* in_sizes, int n_in,
                              void* d_out, int out_size) {
    const float* input = (const float*)d_in[0];
    const float* w_ih0 = (const float*)d_in[1];
    const float* w_hh0 = (const float*)d_in[2];
    const float* b_ih0 = (const float*)d_in[3];
    const float* b_hh0 = (const float*)d_in[4];
    const float* w_ih1 = (const float*)d_in[5];
    const float* w_hh1 = (const float*)d_in[6];
    const float* b_ih1 = (const float*)d_in[7];
    const float* b_hh1 = (const float*)d_in[8];
    const float* w_mlp = (const float*)d_in[9];
    const float* b_mlp = (const float*)d_in[10];

    const int T = 256, IN = 2;
    int B = in_sizes[0] / (T * IN);

    int grid = (B + 63) / 64;      // 16 seqs/warp, 4 warps/block
    lstm_mma3<<<grid, 128>>>(input, w_ih0, w_hh0, b_ih0, b_hh0,
                             w_ih1, w_hh1, b_ih1, b_hh1,
                             w_mlp, b_mlp, (float*)d_out, B);
}

// round 9
// speedup vs baseline: 1.1613x; 1.1613x over previous
#include <cuda_runtime.h>
#include <cuda_bf16.h>
#include <cstdint>

typedef uint32_t u32;

// ---- bf16 helpers ----
__device__ __forceinline__ u32 bf2(float lo, float hi) {   // lo -> low 16 bits
    u32 r; asm("cvt.rn.bf16x2.f32 %0, %1, %2;" : "=r"(r) : "f"(hi), "f"(lo)); return r;
}
__device__ __forceinline__ float lo_f32(u32 p) { return __uint_as_float(p << 16); }
__device__ __forceinline__ float hi_f32(u32 p) { return __uint_as_float(p & 0xFFFF0000u); }
__device__ __forceinline__ float rbf(float v) {
    return __bfloat162float(__float2bfloat16(v));
}

// ---- f32 tanh (MUFU) for the latency-critical c-path ----
__device__ __forceinline__ float tanha(float x) {
    float r; asm("tanh.approx.f32 %0, %1;" : "=f"(r) : "f"(x)); return r;
}

// ---- f16x2 helpers for gate nonlinearities (throughput path) ----
__device__ __forceinline__ u32 pk16(float lo, float hi) {  // lo -> low half
    u32 r; asm("cvt.rn.f16x2.f32 %0, %1, %2;" : "=r"(r) : "f"(hi), "f"(lo)); return r;
}
__device__ __forceinline__ u32 th2(u32 x) {                // 2x tanh, 1 MUFU
    u32 r; asm("tanh.approx.f16x2 %0, %1;" : "=r"(r) : "r"(x)); return r;
}
__device__ __forceinline__ u32 sg2(u32 t) {                // t*0.5 + 0.5 packed
    u32 r; asm("fma.rn.f16x2 %0, %1, %2, %2;" : "=r"(r) : "r"(t), "r"(0x38003800u)); return r;
}
__device__ __forceinline__ u32 hmul2(u32 a, u32 b) {
    u32 r; asm("mul.rn.f16x2 %0, %1, %2;" : "=r"(r) : "r"(a), "r"(b)); return r;
}
__device__ __forceinline__ void up16(u32 p, float& lo, float& hi) {
    asm("{ .reg .b16 l, h; mov.b32 {l, h}, %2; cvt.f32.f16 %0, l; cvt.f32.f16 %1, h; }"
        : "=f"(lo), "=f"(hi) : "r"(p));
}

// D += A * B  (m16n8k16, bf16 in, f32 accum), accumulate in place
__device__ __forceinline__ void mma16816(float* d, u32 a0, u32 a1, u32 a2, u32 a3,
                                         u32 b0, u32 b1) {
    asm("mma.sync.aligned.m16n8k16.row.col.f32.bf16.bf16.f32 "
        "{%0,%1,%2,%3}, {%4,%5,%6,%7}, {%8,%9}, {%0,%1,%2,%3};"
        : "+f"(d[0]), "+f"(d[1]), "+f"(d[2]), "+f"(d[3])
        : "r"(a0), "r"(a1), "r"(a2), "r"(a3), "r"(b0), "r"(b1));
}

// LSTM cell update, 4 cells: gate tanh in f16x2 (8 indep chains -> ILP hides
// cvt latency), c and h strictly f32 (recurrent state carries no f16 error).
// i,f,o prescaled by 0.5 => sigmoid = tanh*0.5+0.5 (packed fma).
__device__ __forceinline__ void cell4(const float (*d)[4], float* c, float* h) {
#pragma unroll
    for (int p = 0; p < 2; p++) {
        int j = p * 2;
        u32 ti = th2(pk16(d[0][j], d[0][j+1]));
        u32 tf = th2(pk16(d[1][j], d[1][j+1]));
        u32 tg = th2(pk16(d[2][j], d[2][j+1]));
        u32 to = th2(pk16(d[3][j], d[3][j+1]));
        u32 iv = sg2(ti), fv = sg2(tf), ov = sg2(to);
        u32 ig = hmul2(iv, tg);
        float ig0, ig1, f0, f1, o0, o1;
        up16(ig, ig0, ig1);
        up16(fv, f0, f1);
        up16(ov, o0, o1);
        c[j]   = fmaf(f0, c[j],   ig0);
        c[j+1] = fmaf(f1, c[j+1], ig1);
        h[j]   = o0 * tanha(c[j]);      // f32 MUFU: short latency on c-path
        h[j+1] = o1 * tanha(c[j+1]);
    }
}

// One warp = 16 sequences. Per step, per gate (depth-2 chained MMAs):
//  L0: d0 = bias + Wih*x (exact f32 FFMA);
//      MMA(d0, [h_hi|h_lo], [Whi|Whi]); MMA(d0, [h_hi|0], [Wlo|Wlo])
//      => full exact-h x full-precision-W.
//  L1: d1 = bias; MMA(d1, [h0hi|h1hi], [Bhi]); MMA(d1, [h0lo|h1lo], [Bhi])
//      => exact-h x bf16-W (only L1's W-lo term dropped).
// Software pipeline: L0(t+1) issued before consuming L1(t).
__global__ void __launch_bounds__(128) lstm_mma4(
    const float* __restrict__ input,
    const float* __restrict__ w_ih0, const float* __restrict__ w_hh0,
    const float* __restrict__ b_ih0, const float* __restrict__ b_hh0,
    const float* __restrict__ w_ih1, const float* __restrict__ w_hh1,
    const float* __restrict__ b_ih1, const float* __restrict__ b_hh1,
    const float* __restrict__ w_mlp, const float* __restrict__ b_mlp,
    float* __restrict__ out, int B)
{
    const int T = 256;
    int lane = threadIdx.x & 31;
    int gid  = lane >> 2;
    int tg   = lane & 3;
    int warp = (blockIdx.x * (blockDim.x >> 5)) + (threadIdx.x >> 5);
    int wbase = warp * 16;

    int rA = wbase + gid;
    int rB = wbase + gid + 8;
    int rAc = (rA < B) ? rA : (B - 1);
    int rBc = (rB < B) ? rB : (B - 1);

    // ---- weights: bf16 B fragments (L0 hi+lo, L1 hi), f32 x-weights, biases ----
    u32 B0h[4], B0l[4], B1a[4], B1b[4];
    float wi00[4], wi01[4], wi10[4], wi11[4];
    float be0[4], bo0[4], be1[4], bo1[4];
#pragma unroll
    for (int g = 0; g < 4; g++) {
        int wr = g * 8 + gid;
        float s = (g == 2) ? 1.0f : 0.5f;
        float a0 = s * w_hh0[wr * 8 + tg * 2], a1 = s * w_hh0[wr * 8 + tg * 2 + 1];
        B0h[g] = bf2(rbf(a0), rbf(a1));
        B0l[g] = bf2(a0 - rbf(a0), a1 - rbf(a1));
        B1a[g] = bf2(s * w_ih1[wr * 8 + tg * 2], s * w_ih1[wr * 8 + tg * 2 + 1]);
        B1b[g] = bf2(s * w_hh1[wr * 8 + tg * 2], s * w_hh1[wr * 8 + tg * 2 + 1]);
        int cE = g * 8 + tg * 2;
        wi00[g] = s * w_ih0[cE * 2];         wi01[g] = s * w_ih0[cE * 2 + 1];
        wi10[g] = s * w_ih0[(cE + 1) * 2];   wi11[g] = s * w_ih0[(cE + 1) * 2 + 1];
        be0[g] = s * (b_ih0[cE] + b_hh0[cE]);
        bo0[g] = s * (b_ih0[cE + 1] + b_hh0[cE + 1]);
        be1[g] = s * (b_ih1[cE] + b_hh1[cE]);
        bo1[g] = s * (b_ih1[cE + 1] + b_hh1[cE + 1]);
    }

    // ---- state ----
    float c0[4] = {0.f, 0.f, 0.f, 0.f};
    float c1[4] = {0.f, 0.f, 0.f, 0.f};
    float h1f[4] = {0.f, 0.f, 0.f, 0.f};
    u32 h0hL = 0, h0hH = 0, h0lL = 0, h0lH = 0;
    u32 h1hL = 0, h1hH = 0, h1lL = 0, h1lH = 0;

    const float2* xr = reinterpret_cast<const float2*>(input);

    // ---- prologue: L0(0) = bias + Wih*x(0); h0(-1)=0 so no MMA ----
    float d0[4][4];
    {
        float2 xA = __ldg(&xr[(size_t)rAc * T]);
        float2 xB = __ldg(&xr[(size_t)rBc * T]);
#pragma unroll
        for (int g = 0; g < 4; g++) {
            d0[g][0] = fmaf(wi01[g], xA.y, fmaf(wi00[g], xA.x, be0[g]));
            d0[g][1] = fmaf(wi11[g], xA.y, fmaf(wi10[g], xA.x, bo0[g]));
            d0[g][2] = fmaf(wi01[g], xB.y, fmaf(wi00[g], xB.x, be0[g]));
            d0[g][3] = fmaf(wi11[g], xB.y, fmaf(wi10[g], xB.x, bo0[g]));
        }
    }

    for (int t = 0; t < T; t++) {
        // ---- consume L0(t) -> h0(t) ----
        float h0f[4];
        cell4(d0, c0, h0f);
        h0hL = bf2(h0f[0], h0f[1]);
        h0lL = bf2(h0f[0] - lo_f32(h0hL), h0f[1] - hi_f32(h0hL));
        h0hH = bf2(h0f[2], h0f[3]);
        h0lH = bf2(h0f[2] - lo_f32(h0hH), h0f[3] - hi_f32(h0hH));

        // ---- issue L1(t): depth-2 chain (exact h, bf16 W) ----
        float d1[4][4];
#pragma unroll
        for (int g = 0; g < 4; g++) {
            d1[g][0] = be1[g]; d1[g][1] = bo1[g];
            d1[g][2] = be1[g]; d1[g][3] = bo1[g];
            mma16816(d1[g], h0hL, h0hH, h1hL, h1hH, B1a[g], B1b[g]);
            mma16816(d1[g], h0lL, h0lH, h1lL, h1lH, B1a[g], B1b[g]);
        }

        // ---- issue L0(t+1): exact x/bias init + depth-2 chain (full W) ----
        {
            int tn = (t < T - 1) ? (t + 1) : t;
            float2 xA = __ldg(&xr[(size_t)rAc * T + tn]);
            float2 xB = __ldg(&xr[(size_t)rBc * T + tn]);
#pragma unroll
            for (int g = 0; g < 4; g++) {
                d0[g][0] = fmaf(wi01[g], xA.y, fmaf(wi00[g], xA.x, be0[g]));
                d0[g][1] = fmaf(wi11[g], xA.y, fmaf(wi10[g], xA.x, bo0[g]));
                d0[g][2] = fmaf(wi01[g], xB.y, fmaf(wi00[g], xB.x, be0[g]));
                d0[g][3] = fmaf(wi11[g], xB.y, fmaf(wi10[g], xB.x, bo0[g]));
                mma16816(d0[g], h0hL, h0hH, h0lL, h0lH, B0h[g], B0h[g]);
                mma16816(d0[g], h0hL, h0hH, 0u, 0u, B0l[g], B0l[g]);
            }
        }

        // ---- consume L1(t) -> h1(t) ----
        cell4(d1, c1, h1f);
        h1hL = bf2(h1f[0], h1f[1]);
        h1lL = bf2(h1f[0] - lo_f32(h1hL), h1f[1] - hi_f32(h1hL));
        h1hH = bf2(h1f[2], h1f[3]);
        h1lH = bf2(h1f[2] - lo_f32(h1hH), h1f[3] - hi_f32(h1hH));
    }

    // ================= MLP head =================
    int hidE = tg * 2;
    float p0A = h1f[0] * w_mlp[hidE]     + h1f[1] * w_mlp[hidE + 1];
    float p1A = h1f[0] * w_mlp[8 + hidE] + h1f[1] * w_mlp[8 + hidE + 1];
    float p0B = h1f[2] * w_mlp[hidE]     + h1f[3] * w_mlp[hidE + 1];
    float p1B = h1f[2] * w_mlp[8 + hidE] + h1f[3] * w_mlp[8 + hidE + 1];
#pragma unroll
    for (int off = 1; off < 4; off <<= 1) {
        p0A += __shfl_xor_sync(0xffffffffu, p0A, off);
        p1A += __shfl_xor_sync(0xffffffffu, p1A, off);
        p0B += __shfl_xor_sync(0xffffffffu, p0B, off);
        p1B += __shfl_xor_sync(0xffffffffu, p1B, off);
    }
    if (tg == 0) {
        if (rA < B) {
            float2 o; o.x = p0A + b_mlp[0]; o.y = p1A + b_mlp[1];
            reinterpret_cast<float2*>(out)[rA] = o;
        }
        if (rB < B) {
            float2 o; o.x = p0B + b_mlp[0]; o.y = p1B + b_mlp[1];
            reinterpret_cast<float2*>(out)[rB] = o;
        }
    }
}

extern "C" void kernel_launch(void* const* d_in, const int* in_sizes, int n_in,
                              void* d_out, int out_size) {
    const float* input = (const float*)d_in[0];
    const float* w_ih0 = (const float*)d_in[1];
    const float* w_hh0 = (const float*)d_in[2];
    const float* b_ih0 = (const float*)d_in[3];
    const float* b_hh0 = (const float*)d_in[4];
    const float* w_ih1 = (const float*)d_in[5];
    const float* w_hh1 = (const float*)d_in[6];
    const float* b_ih1 = (const float*)d_in[7];
    const float* b_hh1 = (const float*)d_in[8];
    const float* w_mlp = (const float*)d_in[9];
    const float* b_mlp = (const float*)d_in[10];

    const int T = 256, IN = 2;
    int B = in_sizes[0] / (T * IN);

    int grid = (B + 63) / 64;      // 16 seqs/warp, 4 warps/block
    lstm_mma4<<<grid, 128>>>(input, w_ih0, w_hh0, b_ih0, b_hh0,
                             w_ih1, w_hh1, b_ih1, b_hh1,
                             w_mlp, b_mlp, (float*)d_out, B);
}

// round 10
// speedup vs baseline: 1.1731x; 1.0101x over previous
#include <cuda_runtime.h>
#include <cuda_bf16.h>
#include <cstdint>

typedef uint32_t u32;

// ---- bf16 helpers ----
__device__ __forceinline__ u32 bf2(float lo, float hi) {   // lo -> low 16 bits
    u32 r; asm("cvt.rn.bf16x2.f32 %0, %1, %2;" : "=r"(r) : "f"(hi), "f"(lo)); return r;
}
__device__ __forceinline__ float lo_f32(u32 p) { return __uint_as_float(p << 16); }
__device__ __forceinline__ float hi_f32(u32 p) { return __uint_as_float(p & 0xFFFF0000u); }
__device__ __forceinline__ float rbf(float v) {
    return __bfloat162float(__float2bfloat16(v));
}

// ---- f32 tanh (MUFU) ----
__device__ __forceinline__ float tanha(float x) {
    float r; asm("tanh.approx.f32 %0, %1;" : "=f"(r) : "f"(x)); return r;
}
// sigmoid(z) = 0.5*tanh(z/2)+0.5; /2 pre-folded into weights+biases
__device__ __forceinline__ float sigp(float hz) { return fmaf(tanha(hz), 0.5f, 0.5f); }

// D += A * B  (m16n8k16, bf16 in, f32 accum), accumulate in place
__device__ __forceinline__ void mma16816(float* d, u32 a0, u32 a1, u32 a2, u32 a3,
                                         u32 b0, u32 b1) {
    asm("mma.sync.aligned.m16n8k16.row.col.f32.bf16.bf16.f32 "
        "{%0,%1,%2,%3}, {%4,%5,%6,%7}, {%8,%9}, {%0,%1,%2,%3};"
        : "+f"(d[0]), "+f"(d[1]), "+f"(d[2]), "+f"(d[3])
        : "r"(a0), "r"(a1), "r"(a2), "r"(a3), "r"(b0), "r"(b1));
}

// LSTM cell update, 4 cells, pure f32 (proven fastest + most accurate):
// i,f,o prescaled by 0.5 => sigmoid = tanh*0.5+0.5.
__device__ __forceinline__ void cell4(const float (*d)[4], float* c, float* h) {
#pragma unroll
    for (int j = 0; j < 4; j++) {
        float iv = sigp(d[0][j]);
        float fv = sigp(d[1][j]);
        float gv = tanha(d[2][j]);
        float ov = sigp(d[3][j]);
        c[j] = fmaf(fv, c[j], iv * gv);
        h[j] = ov * tanha(c[j]);
    }
}

// One warp = 16 sequences; 2-warp (64-thread) blocks => grid ~= 1024 for near-
// perfect SM load balance (7 vs 6.92 blocks/SM; the 128-thread version left
// 68 SMs pacing the chip 16% slower).
// Per step, per gate:
//  L0 (depth 2): d0 = bias + Wih*x (exact f32 FFMA);
//      MMA(d0, [h_hi|h_lo], [Whi|Whi]); MMA(d0, [h_hi|0], [Wlo|Wlo]).
//  L1 (depth 3): d1 = bias; MMA(d1,[h0hi|h1hi],[Bhi]); MMA(d1,[h0lo|h1lo],[Bhi]);
//      MMA(d1,[h0hi|h1hi],[Blo])  => full hi/lo product, no dropped W terms.
// Software pipeline: L0(t+1) issued before consuming L1(t).
__global__ void __launch_bounds__(64, 7) lstm_mma5(
    const float* __restrict__ input,
    const float* __restrict__ w_ih0, const float* __restrict__ w_hh0,
    const float* __restrict__ b_ih0, const float* __restrict__ b_hh0,
    const float* __restrict__ w_ih1, const float* __restrict__ w_hh1,
    const float* __restrict__ b_ih1, const float* __restrict__ b_hh1,
    const float* __restrict__ w_mlp, const float* __restrict__ b_mlp,
    float* __restrict__ out, int B)
{
    const int T = 256;
    int lane = threadIdx.x & 31;
    int gid  = lane >> 2;
    int tg   = lane & 3;
    int warp = (blockIdx.x * (blockDim.x >> 5)) + (threadIdx.x >> 5);
    int wbase = warp * 16;

    int rA = wbase + gid;
    int rB = wbase + gid + 8;
    int rAc = (rA < B) ? rA : (B - 1);
    int rBc = (rB < B) ? rB : (B - 1);

    // ---- weights: bf16 hi+lo B fragments, f32 x-weights, f32 biases ----
    u32 B0h[4], B0l[4], B1ah[4], B1bh[4], B1al[4], B1bl[4];
    float wi00[4], wi01[4], wi10[4], wi11[4];
    float be0[4], bo0[4], be1[4], bo1[4];
#pragma unroll
    for (int g = 0; g < 4; g++) {
        int wr = g * 8 + gid;
        float s = (g == 2) ? 1.0f : 0.5f;
        float a0 = s * w_hh0[wr * 8 + tg * 2], a1 = s * w_hh0[wr * 8 + tg * 2 + 1];
        float u0 = s * w_ih1[wr * 8 + tg * 2], u1 = s * w_ih1[wr * 8 + tg * 2 + 1];
        float v0 = s * w_hh1[wr * 8 + tg * 2], v1 = s * w_hh1[wr * 8 + tg * 2 + 1];
        B0h[g]  = bf2(rbf(a0), rbf(a1));  B0l[g]  = bf2(a0 - rbf(a0), a1 - rbf(a1));
        B1ah[g] = bf2(rbf(u0), rbf(u1));  B1al[g] = bf2(u0 - rbf(u0), u1 - rbf(u1));
        B1bh[g] = bf2(rbf(v0), rbf(v1));  B1bl[g] = bf2(v0 - rbf(v0), v1 - rbf(v1));
        int cE = g * 8 + tg * 2;
        wi00[g] = s * w_ih0[cE * 2];         wi01[g] = s * w_ih0[cE * 2 + 1];
        wi10[g] = s * w_ih0[(cE + 1) * 2];   wi11[g] = s * w_ih0[(cE + 1) * 2 + 1];
        be0[g] = s * (b_ih0[cE] + b_hh0[cE]);
        bo0[g] = s * (b_ih0[cE + 1] + b_hh0[cE + 1]);
        be1[g] = s * (b_ih1[cE] + b_hh1[cE]);
        bo1[g] = s * (b_ih1[cE + 1] + b_hh1[cE + 1]);
    }

    // ---- state ----
    float c0[4] = {0.f, 0.f, 0.f, 0.f};
    float c1[4] = {0.f, 0.f, 0.f, 0.f};
    float h1f[4] = {0.f, 0.f, 0.f, 0.f};
    u32 h0hL = 0, h0hH = 0, h0lL = 0, h0lH = 0;
    u32 h1hL = 0, h1hH = 0, h1lL = 0, h1lH = 0;

    const float2* xr = reinterpret_cast<const float2*>(input);

    // ---- prologue: L0(0) = bias + Wih*x(0); h0(-1)=0 so no MMA ----
    float d0[4][4];
    {
        float2 xA = __ldg(&xr[(size_t)rAc * T]);
        float2 xB = __ldg(&xr[(size_t)rBc * T]);
#pragma unroll
        for (int g = 0; g < 4; g++) {
            d0[g][0] = fmaf(wi01[g], xA.y, fmaf(wi00[g], xA.x, be0[g]));
            d0[g][1] = fmaf(wi11[g], xA.y, fmaf(wi10[g], xA.x, bo0[g]));
            d0[g][2] = fmaf(wi01[g], xB.y, fmaf(wi00[g], xB.x, be0[g]));
            d0[g][3] = fmaf(wi11[g], xB.y, fmaf(wi10[g], xB.x, bo0[g]));
        }
    }

    for (int t = 0; t < T; t++) {
        // ---- consume L0(t) -> h0(t) ----
        float h0f[4];
        cell4(d0, c0, h0f);
        h0hL = bf2(h0f[0], h0f[1]);
        h0lL = bf2(h0f[0] - lo_f32(h0hL), h0f[1] - hi_f32(h0hL));
        h0hH = bf2(h0f[2], h0f[3]);
        h0lH = bf2(h0f[2] - lo_f32(h0hH), h0f[3] - hi_f32(h0hH));

        // ---- issue L1(t): depth-3 chain, full hi/lo product ----
        float d1[4][4];
#pragma unroll
        for (int g = 0; g < 4; g++) {
            d1[g][0] = be1[g]; d1[g][1] = bo1[g];
            d1[g][2] = be1[g]; d1[g][3] = bo1[g];
            mma16816(d1[g], h0hL, h0hH, h1hL, h1hH, B1ah[g], B1bh[g]);
            mma16816(d1[g], h0lL, h0lH, h1lL, h1lH, B1ah[g], B1bh[g]);
            mma16816(d1[g], h0hL, h0hH, h1hL, h1hH, B1al[g], B1bl[g]);
        }

        // ---- issue L0(t+1): exact x/bias init + depth-2 chain (full W) ----
        {
            int tn = (t < T - 1) ? (t + 1) : t;
            float2 xA = __ldg(&xr[(size_t)rAc * T + tn]);
            float2 xB = __ldg(&xr[(size_t)rBc * T + tn]);
#pragma unroll
            for (int g = 0; g < 4; g++) {
                d0[g][0] = fmaf(wi01[g], xA.y, fmaf(wi00[g], xA.x, be0[g]));
                d0[g][1] = fmaf(wi11[g], xA.y, fmaf(wi10[g], xA.x, bo0[g]));
                d0[g][2] = fmaf(wi01[g], xB.y, fmaf(wi00[g], xB.x, be0[g]));
                d0[g][3] = fmaf(wi11[g], xB.y, fmaf(wi10[g], xB.x, bo0[g]));
                mma16816(d0[g], h0hL, h0hH, h0lL, h0lH, B0h[g], B0h[g]);
                mma16816(d0[g], h0hL, h0hH, 0u, 0u, B0l[g], B0l[g]);
            }
        }

        // ---- consume L1(t) -> h1(t) ----
        cell4(d1, c1, h1f);
        h1hL = bf2(h1f[0], h1f[1]);
        h1lL = bf2(h1f[0] - lo_f32(h1hL), h1f[1] - hi_f32(h1hL));
        h1hH = bf2(h1f[2], h1f[3]);
        h1lH = bf2(h1f[2] - lo_f32(h1hH), h1f[3] - hi_f32(h1hH));
    }

    // ================= MLP head =================
    int hidE = tg * 2;
    float p0A = h1f[0] * w_mlp[hidE]     + h1f[1] * w_mlp[hidE + 1];
    float p1A = h1f[0] * w_mlp[8 + hidE] + h1f[1] * w_mlp[8 + hidE + 1];
    float p0B = h1f[2] * w_mlp[hidE]     + h1f[3] * w_mlp[hidE + 1];
    float p1B = h1f[2] * w_mlp[8 + hidE] + h1f[3] * w_mlp[8 + hidE + 1];
#pragma unroll
    for (int off = 1; off < 4; off <<= 1) {
        p0A += __shfl_xor_sync(0xffffffffu, p0A, off);
        p1A += __shfl_xor_sync(0xffffffffu, p1A, off);
        p0B += __shfl_xor_sync(0xffffffffu, p0B, off);
        p1B += __shfl_xor_sync(0xffffffffu, p1B, off);
    }
    if (tg == 0) {
        if (rA < B) {
            float2 o; o.x = p0A + b_mlp[0]; o.y = p1A + b_mlp[1];
            reinterpret_cast<float2*>(out)[rA] = o;
        }
        if (rB < B) {
            float2 o; o.x = p0B + b_mlp[0]; o.y = p1B + b_mlp[1];
            reinterpret_cast<float2*>(out)[rB] = o;
        }
    }
}

extern "C" void kernel_launch(void* const* d_in, const int* in_sizes, int n_in,
                              void* d_out, int out_size) {
    const float* input = (const float*)d_in[0];
    const float* w_ih0 = (const float*)d_in[1];
    const float* w_hh0 = (const float*)d_in[2];
    const float* b_ih0 = (const float*)d_in[3];
    const float* b_hh0 = (const float*)d_in[4];
    const float* w_ih1 = (const float*)d_in[5];
    const float* w_hh1 = (const float*)d_in[6];
    const float* b_ih1 = (const float*)d_in[7];
    const float* b_hh1 = (const float*)d_in[8];
    const float* w_mlp = (const float*)d_in[9];
    const float* b_mlp = (const float*)d_in[10];

    const int T = 256, IN = 2;
    int B = in_sizes[0] / (T * IN);

    // 16 seqs/warp, 2 warps/block (64 threads) => 32 seqs/block
    int grid = (B + 31) / 32;
    lstm_mma5<<<grid, 64>>>(input, w_ih0, w_hh0, b_ih0, b_hh0,
                            w_ih1, w_hh1, b_ih1, b_hh1,
                            w_mlp, b_mlp, (float*)d_out, B);
}